// round 9
// baseline (speedup 1.0000x reference)
#include <cuda_runtime.h>

#define B_   32
#define C_   256
#define H_   80
#define W_   80
#define HWv  6400
#define MID_ 64
#define H2_  160
#define W2_  160

// Scratch: per (b, subpixel o in 0..3, h, w) the clipped source-space sample coord (ix, iy).
__device__ float2 g_coords[B_ * 4 * HWv];

__device__ __forceinline__ unsigned long long pack2(float lo, float hi) {
    unsigned long long r;
    asm("mov.b64 %0, {%1, %2};" : "=l"(r) : "f"(lo), "f"(hi));
    return r;
}
__device__ __forceinline__ void unpack2(unsigned long long v, float& lo, float& hi) {
    asm("mov.b64 {%0, %1}, %2;" : "=f"(lo), "=f"(hi) : "l"(v));
}
// Packed fp32x2 FMA (Blackwell; PTX-only, ptxas never auto-fuses).
__device__ __forceinline__ unsigned long long ffma2(unsigned long long a,
                                                    unsigned long long b,
                                                    unsigned long long c) {
    unsigned long long d;
    asm("fma.rn.f32x2 %0, %1, %2, %3;" : "=l"(d) : "l"(a), "l"(b), "l"(c));
    return d;
}

// ---------------------------------------------------------------------------
// Kernel A: per input pixel compute hid = relu(W1 x), off = tanh(W2 hid + b2),
// then the 4 subpixel sample coordinates (clipped to [0, 79]).
// 256 threads/block, 2 pixels/thread, W1 in shared as f32x2 pairs [c][m/2].
// ---------------------------------------------------------------------------
__global__ __launch_bounds__(256, 1)
void dysample_offsets(const float* __restrict__ x, const float* __restrict__ w1,
                      const float* __restrict__ w2, const float* __restrict__ b2) {
    extern __shared__ unsigned long long smem_u64[];
    unsigned long long* sw1 = smem_u64;                 // [256][32] packed pairs (64 KB)
    float* sw2 = (float*)(smem_u64 + C_ * 32);          // [8][64]
    float* sb2 = sw2 + 8 * 64;                          // [8]

    const int t = threadIdx.x;
    for (int idx = t; idx < C_ * 32; idx += 256) {
        int c = idx >> 5, m2 = idx & 31;
        sw1[idx] = pack2(w1[(2 * m2) * C_ + c], w1[(2 * m2 + 1) * C_ + c]);
    }
    for (int idx = t; idx < 512; idx += 256) sw2[idx] = w2[idx];
    if (t < 8) sb2[t] = b2[t];
    __syncthreads();

    const int P0 = blockIdx.x * 512 + t;   // 400 blocks * 512 pixels = 204800
    const int P1 = P0 + 256;
    const int b0 = P0 / HWv, p0 = P0 - b0 * HWv;
    const int b1 = P1 / HWv, p1 = P1 - b1 * HWv;
    const float* xp0 = x + (size_t)b0 * C_ * HWv + p0;
    const float* xp1 = x + (size_t)b1 * C_ * HWv + p1;

    unsigned long long acc0[32], acc1[32];
    #pragma unroll
    for (int m2 = 0; m2 < 32; m2++) { acc0[m2] = 0ULL; acc1[m2] = 0ULL; }

    // Software pipeline: prefetch next 8-channel x block while FMAing current.
    float cur0[8], cur1[8];
    #pragma unroll
    for (int k = 0; k < 8; k++) { cur0[k] = xp0[k * HWv]; cur1[k] = xp1[k * HWv]; }

    #pragma unroll 1
    for (int cb = 0; cb < C_; cb += 8) {
        float nxt0[8], nxt1[8];
        if (cb + 8 < C_) {
            #pragma unroll
            for (int k = 0; k < 8; k++) {
                nxt0[k] = xp0[(cb + 8 + k) * HWv];
                nxt1[k] = xp1[(cb + 8 + k) * HWv];
            }
        }
        #pragma unroll
        for (int k = 0; k < 8; k++) {
            unsigned long long xv0 = pack2(cur0[k], cur0[k]);
            unsigned long long xv1 = pack2(cur1[k], cur1[k]);
            const unsigned long long* wrow = sw1 + (cb + k) * 32;
            #pragma unroll
            for (int m2 = 0; m2 < 32; m2++) {
                unsigned long long wv = wrow[m2];   // one LDS.64 serves 2 FFMA2
                acc0[m2] = ffma2(xv0, wv, acc0[m2]);
                acc1[m2] = ffma2(xv1, wv, acc1[m2]);
            }
        }
        #pragma unroll
        for (int k = 0; k < 8; k++) { cur0[k] = nxt0[k]; cur1[k] = nxt1[k]; }
    }

    // ReLU in place.
    #pragma unroll
    for (int m2 = 0; m2 < 32; m2++) {
        float lo, hi;
        unpack2(acc0[m2], lo, hi);
        acc0[m2] = pack2(fmaxf(lo, 0.f), fmaxf(hi, 0.f));
        unpack2(acc1[m2], lo, hi);
        acc1[m2] = pack2(fmaxf(lo, 0.f), fmaxf(hi, 0.f));
    }

    // Stage 2: off[o] = tanh(W2[o,:] . hid + b2[o]),  o=0..3 -> off_x, 4..7 -> off_y
    float off0[8], off1[8];
    #pragma unroll
    for (int o = 0; o < 8; o++) {
        float s0 = sb2[o], s1 = s0;
        const float* wr = sw2 + o * 64;
        #pragma unroll
        for (int m2 = 0; m2 < 32; m2++) {
            float lo, hi;
            unpack2(acc0[m2], lo, hi);
            s0 = fmaf(lo, wr[2 * m2], s0);
            s0 = fmaf(hi, wr[2 * m2 + 1], s0);
            unpack2(acc1[m2], lo, hi);
            s1 = fmaf(lo, wr[2 * m2], s1);
            s1 = fmaf(hi, wr[2 * m2 + 1], s1);
        }
        off0[o] = tanhf(s0);
        off1[o] = tanhf(s1);
    }

    // Sample coords.
    // x2 = 2w+j : sx = (2*x2+1)/160 - 1 + off_x * (2/160)
    // ix = clip((sx+1)*0.5*79) = (4w+2j+1)*(39.5/160) + off_x*(79/160), clipped [0,79].
    const float A = 0.246875f;   // 39.5/160
    const float Bc = 0.49375f;   // 79/160
    const int h0 = p0 / W_, w0 = p0 - h0 * W_;
    const int h1 = p1 / W_, w1c = p1 - h1 * W_;
    #pragma unroll
    for (int o = 0; o < 4; o++) {
        int j = o & 1, i = o >> 1;
        float ix, iy;
        ix = fminf(fmaxf((float)(4 * w0 + 2 * j + 1) * A + off0[o] * Bc, 0.f), 79.f);
        iy = fminf(fmaxf((float)(4 * h0 + 2 * i + 1) * A + off0[o + 4] * Bc, 0.f), 79.f);
        g_coords[(b0 * 4 + o) * HWv + p0] = make_float2(ix, iy);
        ix = fminf(fmaxf((float)(4 * w1c + 2 * j + 1) * A + off1[o] * Bc, 0.f), 79.f);
        iy = fminf(fmaxf((float)(4 * h1 + 2 * i + 1) * A + off1[o + 4] * Bc, 0.f), 79.f);
        g_coords[(b1 * 4 + o) * HWv + p1] = make_float2(ix, iy);
    }
}

// ---------------------------------------------------------------------------
// Kernel B: bilinear gather. Thread = one (y2, x2) output position; computes
// bilinear weights/offsets ONCE, loops over 256 channels (4 gathers + 1 store).
// Warp = 32 consecutive x2 in one y2 row -> fully coalesced 128B stores.
// ---------------------------------------------------------------------------
__global__ __launch_bounds__(256)
void dysample_sample(const float* __restrict__ x, float* __restrict__ out) {
    const int lane = threadIdx.x & 31;
    const int warp = threadIdx.x >> 5;
    const int y2 = blockIdx.y * 8 + warp;
    const int x2 = blockIdx.x * 32 + lane;
    const int b = blockIdx.z;
    const int h = y2 >> 1, w = x2 >> 1;
    const int o = ((y2 & 1) << 1) | (x2 & 1);

    const float2 cd = g_coords[(b * 4 + o) * HWv + h * W_ + w];
    const float fx = floorf(cd.x), fy = floorf(cd.y);
    const int x0 = (int)fx, y0 = (int)fy;
    const int x1 = min(x0 + 1, W_ - 1), y1 = min(y0 + 1, H_ - 1);
    const float wx = cd.x - fx, wy = cd.y - fy;
    const float w00 = (1.f - wx) * (1.f - wy);
    const float w01 = wx * (1.f - wy);
    const float w10 = (1.f - wx) * wy;
    const float w11 = wx * wy;
    const int o00 = y0 * W_ + x0, o01 = y0 * W_ + x1;
    const int o10 = y1 * W_ + x0, o11 = y1 * W_ + x1;

    const float* xb = x + (size_t)b * C_ * HWv;
    float* ob = out + (size_t)b * C_ * (H2_ * W2_) + y2 * W2_ + x2;

    #pragma unroll 4
    for (int c = 0; c < C_; c++) {
        const float* pl = xb + c * HWv;
        float v = __ldg(pl + o00) * w00 + __ldg(pl + o01) * w01
                + __ldg(pl + o10) * w10 + __ldg(pl + o11) * w11;
        ob[(size_t)c * (H2_ * W2_)] = v;
    }
}

extern "C" void kernel_launch(void* const* d_in, const int* in_sizes, int n_in,
                              void* d_out, int out_size) {
    const float* x  = (const float*)d_in[0];
    const float* w1 = (const float*)d_in[1];
    const float* w2 = (const float*)d_in[2];
    const float* b2 = (const float*)d_in[3];
    float* out = (float*)d_out;

    const int smemA = C_ * 32 * 8 + 512 * 4 + 8 * 4;   // 67616 bytes
    cudaFuncSetAttribute(dysample_offsets,
                         cudaFuncAttributeMaxDynamicSharedMemorySize, smemA);

    dysample_offsets<<<400, 256, smemA>>>(x, w1, w2, b2);

    dim3 gridB(W2_ / 32, H2_ / 8, B_);   // (5, 20, 32)
    dysample_sample<<<gridB, 256>>>(x, out);
}

// round 10
// speedup vs baseline: 1.0086x; 1.0086x over previous
#include <cuda_runtime.h>

#define B_   32
#define C_   256
#define H_   80
#define W_   80
#define HWv  6400
#define MID_ 64
#define H2_  160
#define W2_  160

// Scratch: per (b, subpixel o in 0..3, h, w) the clipped source-space sample coord (ix, iy).
__device__ float2 g_coords[B_ * 4 * HWv];

__device__ __forceinline__ unsigned long long pack2(float lo, float hi) {
    unsigned long long r;
    asm("mov.b64 %0, {%1, %2};" : "=l"(r) : "f"(lo), "f"(hi));
    return r;
}
__device__ __forceinline__ void unpack2(unsigned long long v, float& lo, float& hi) {
    asm("mov.b64 {%0, %1}, %2;" : "=f"(lo), "=f"(hi) : "l"(v));
}
// Packed fp32x2 FMA (Blackwell; PTX-only, ptxas never auto-fuses).
__device__ __forceinline__ unsigned long long ffma2(unsigned long long a,
                                                    unsigned long long b,
                                                    unsigned long long c) {
    unsigned long long d;
    asm("fma.rn.f32x2 %0, %1, %2, %3;" : "=l"(d) : "l"(a), "l"(b), "l"(c));
    return d;
}

// ---------------------------------------------------------------------------
// Kernel A: per input pixel compute hid = relu(W1 x), off = tanh(W2 hid + b2),
// then the 4 subpixel sample coordinates (clipped to [0, 79]).
// 256 threads/block, 2 pixels/thread, W1 in shared as f32x2 pairs [c][m/2].
// ---------------------------------------------------------------------------
__global__ __launch_bounds__(256, 1)
void dysample_offsets(const float* __restrict__ x, const float* __restrict__ w1,
                      const float* __restrict__ w2, const float* __restrict__ b2) {
    extern __shared__ unsigned long long smem_u64[];
    unsigned long long* sw1 = smem_u64;                 // [256][32] packed pairs (64 KB)
    float* sw2 = (float*)(smem_u64 + C_ * 32);          // [8][64]
    float* sb2 = sw2 + 8 * 64;                          // [8]

    const int t = threadIdx.x;
    for (int idx = t; idx < C_ * 32; idx += 256) {
        int c = idx >> 5, m2 = idx & 31;
        sw1[idx] = pack2(w1[(2 * m2) * C_ + c], w1[(2 * m2 + 1) * C_ + c]);
    }
    for (int idx = t; idx < 512; idx += 256) sw2[idx] = w2[idx];
    if (t < 8) sb2[t] = b2[t];
    __syncthreads();

    const int P0 = blockIdx.x * 512 + t;   // 400 blocks * 512 pixels = 204800
    const int P1 = P0 + 256;
    const int b0 = P0 / HWv, p0 = P0 - b0 * HWv;
    const int b1 = P1 / HWv, p1 = P1 - b1 * HWv;
    const float* xp0 = x + (size_t)b0 * C_ * HWv + p0;
    const float* xp1 = x + (size_t)b1 * C_ * HWv + p1;

    unsigned long long acc0[32], acc1[32];
    #pragma unroll
    for (int m2 = 0; m2 < 32; m2++) { acc0[m2] = 0ULL; acc1[m2] = 0ULL; }

    // Software pipeline: prefetch next 8-channel x block while FMAing current.
    float cur0[8], cur1[8];
    #pragma unroll
    for (int k = 0; k < 8; k++) { cur0[k] = xp0[k * HWv]; cur1[k] = xp1[k * HWv]; }

    #pragma unroll 1
    for (int cb = 0; cb < C_; cb += 8) {
        float nxt0[8], nxt1[8];
        if (cb + 8 < C_) {
            #pragma unroll
            for (int k = 0; k < 8; k++) {
                nxt0[k] = xp0[(cb + 8 + k) * HWv];
                nxt1[k] = xp1[(cb + 8 + k) * HWv];
            }
        }
        #pragma unroll
        for (int k = 0; k < 8; k++) {
            unsigned long long xv0 = pack2(cur0[k], cur0[k]);
            unsigned long long xv1 = pack2(cur1[k], cur1[k]);
            const unsigned long long* wrow = sw1 + (cb + k) * 32;
            #pragma unroll
            for (int m2 = 0; m2 < 32; m2++) {
                unsigned long long wv = wrow[m2];   // one LDS.64 serves 2 FFMA2
                acc0[m2] = ffma2(xv0, wv, acc0[m2]);
                acc1[m2] = ffma2(xv1, wv, acc1[m2]);
            }
        }
        #pragma unroll
        for (int k = 0; k < 8; k++) { cur0[k] = nxt0[k]; cur1[k] = nxt1[k]; }
    }

    // ReLU in place.
    #pragma unroll
    for (int m2 = 0; m2 < 32; m2++) {
        float lo, hi;
        unpack2(acc0[m2], lo, hi);
        acc0[m2] = pack2(fmaxf(lo, 0.f), fmaxf(hi, 0.f));
        unpack2(acc1[m2], lo, hi);
        acc1[m2] = pack2(fmaxf(lo, 0.f), fmaxf(hi, 0.f));
    }

    // Stage 2: off[o] = tanh(W2[o,:] . hid + b2[o]),  o=0..3 -> off_x, 4..7 -> off_y
    float off0[8], off1[8];
    #pragma unroll
    for (int o = 0; o < 8; o++) {
        float s0 = sb2[o], s1 = s0;
        const float* wr = sw2 + o * 64;
        #pragma unroll
        for (int m2 = 0; m2 < 32; m2++) {
            float lo, hi;
            unpack2(acc0[m2], lo, hi);
            s0 = fmaf(lo, wr[2 * m2], s0);
            s0 = fmaf(hi, wr[2 * m2 + 1], s0);
            unpack2(acc1[m2], lo, hi);
            s1 = fmaf(lo, wr[2 * m2], s1);
            s1 = fmaf(hi, wr[2 * m2 + 1], s1);
        }
        off0[o] = tanhf(s0);
        off1[o] = tanhf(s1);
    }

    // Sample coords.
    // x2 = 2w+j : sx = (2*x2+1)/160 - 1 + off_x * (2/160)
    // ix = clip((sx+1)*0.5*79) = (4w+2j+1)*(39.5/160) + off_x*(79/160), clipped [0,79].
    const float A = 0.246875f;   // 39.5/160
    const float Bc = 0.49375f;   // 79/160
    const int h0 = p0 / W_, w0 = p0 - h0 * W_;
    const int h1 = p1 / W_, w1c = p1 - h1 * W_;
    #pragma unroll
    for (int o = 0; o < 4; o++) {
        int j = o & 1, i = o >> 1;
        float ix, iy;
        ix = fminf(fmaxf((float)(4 * w0 + 2 * j + 1) * A + off0[o] * Bc, 0.f), 79.f);
        iy = fminf(fmaxf((float)(4 * h0 + 2 * i + 1) * A + off0[o + 4] * Bc, 0.f), 79.f);
        g_coords[(b0 * 4 + o) * HWv + p0] = make_float2(ix, iy);
        ix = fminf(fmaxf((float)(4 * w1c + 2 * j + 1) * A + off1[o] * Bc, 0.f), 79.f);
        iy = fminf(fmaxf((float)(4 * h1 + 2 * i + 1) * A + off1[o + 4] * Bc, 0.f), 79.f);
        g_coords[(b1 * 4 + o) * HWv + p1] = make_float2(ix, iy);
    }
}

// ---------------------------------------------------------------------------
// Kernel B: bilinear gather. Thread = one (y2, x2) output position; computes
// bilinear weights/offsets ONCE, loops over 256 channels (4 gathers + 1 store).
// Warp = 32 consecutive x2 in one y2 row -> fully coalesced 128B stores.
// ---------------------------------------------------------------------------
__global__ __launch_bounds__(256)
void dysample_sample(const float* __restrict__ x, float* __restrict__ out) {
    const int lane = threadIdx.x & 31;
    const int warp = threadIdx.x >> 5;
    const int y2 = blockIdx.y * 8 + warp;
    const int x2 = blockIdx.x * 32 + lane;
    const int b = blockIdx.z;
    const int h = y2 >> 1, w = x2 >> 1;
    const int o = ((y2 & 1) << 1) | (x2 & 1);

    const float2 cd = g_coords[(b * 4 + o) * HWv + h * W_ + w];
    const float fx = floorf(cd.x), fy = floorf(cd.y);
    const int x0 = (int)fx, y0 = (int)fy;
    const int x1 = min(x0 + 1, W_ - 1), y1 = min(y0 + 1, H_ - 1);
    const float wx = cd.x - fx, wy = cd.y - fy;
    const float w00 = (1.f - wx) * (1.f - wy);
    const float w01 = wx * (1.f - wy);
    const float w10 = (1.f - wx) * wy;
    const float w11 = wx * wy;
    const int o00 = y0 * W_ + x0, o01 = y0 * W_ + x1;
    const int o10 = y1 * W_ + x0, o11 = y1 * W_ + x1;

    const float* xb = x + (size_t)b * C_ * HWv;
    float* ob = out + (size_t)b * C_ * (H2_ * W2_) + y2 * W2_ + x2;

    #pragma unroll 4
    for (int c = 0; c < C_; c++) {
        const float* pl = xb + c * HWv;
        float v = __ldg(pl + o00) * w00 + __ldg(pl + o01) * w01
                + __ldg(pl + o10) * w10 + __ldg(pl + o11) * w11;
        ob[(size_t)c * (H2_ * W2_)] = v;
    }
}

extern "C" void kernel_launch(void* const* d_in, const int* in_sizes, int n_in,
                              void* d_out, int out_size) {
    const float* x  = (const float*)d_in[0];
    const float* w1 = (const float*)d_in[1];
    const float* w2 = (const float*)d_in[2];
    const float* b2 = (const float*)d_in[3];
    float* out = (float*)d_out;

    const int smemA = C_ * 32 * 8 + 512 * 4 + 8 * 4;   // 67616 bytes
    cudaFuncSetAttribute(dysample_offsets,
                         cudaFuncAttributeMaxDynamicSharedMemorySize, smemA);

    dysample_offsets<<<400, 256, smemA>>>(x, w1, w2, b2);

    dim3 gridB(W2_ / 32, H2_ / 8, B_);   // (5, 20, 32)
    dysample_sample<<<gridB, 256>>>(x, out);
}

// round 11
// speedup vs baseline: 1.0118x; 1.0032x over previous
#include <cuda_runtime.h>

#define B_   32
#define C_   256
#define H_   80
#define W_   80
#define HWv  6400
#define MID_ 64
#define H2_  160
#define W2_  160

// Scratch: per (b, subpixel o in 0..3, h, w) the clipped source-space sample coord (ix, iy).
__device__ float2 g_coords[B_ * 4 * HWv];

__device__ __forceinline__ unsigned long long pack2(float lo, float hi) {
    unsigned long long r;
    asm("mov.b64 %0, {%1, %2};" : "=l"(r) : "f"(lo), "f"(hi));
    return r;
}
__device__ __forceinline__ void unpack2(unsigned long long v, float& lo, float& hi) {
    asm("mov.b64 {%0, %1}, %2;" : "=f"(lo), "=f"(hi) : "l"(v));
}
// Packed fp32x2 FMA (Blackwell; PTX-only, ptxas never auto-fuses).
__device__ __forceinline__ unsigned long long ffma2(unsigned long long a,
                                                    unsigned long long b,
                                                    unsigned long long c) {
    unsigned long long d;
    asm("fma.rn.f32x2 %0, %1, %2, %3;" : "=l"(d) : "l"(a), "l"(b), "l"(c));
    return d;
}

// ---------------------------------------------------------------------------
// Kernel A: per input pixel compute hid = relu(W1 x), off = tanh(W2 hid + b2),
// then the 4 subpixel sample coordinates (clipped to [0, 79]).
// 256 threads/block, 2 pixels/thread, W1 in shared as f32x2 pairs [c][m/2].
// ---------------------------------------------------------------------------
__global__ __launch_bounds__(256, 1)
void dysample_offsets(const float* __restrict__ x, const float* __restrict__ w1,
                      const float* __restrict__ w2, const float* __restrict__ b2) {
    extern __shared__ unsigned long long smem_u64[];
    unsigned long long* sw1 = smem_u64;                 // [256][32] packed pairs (64 KB)
    float* sw2 = (float*)(smem_u64 + C_ * 32);          // [8][64]
    float* sb2 = sw2 + 8 * 64;                          // [8]

    const int t = threadIdx.x;
    for (int idx = t; idx < C_ * 32; idx += 256) {
        int c = idx >> 5, m2 = idx & 31;
        sw1[idx] = pack2(w1[(2 * m2) * C_ + c], w1[(2 * m2 + 1) * C_ + c]);
    }
    for (int idx = t; idx < 512; idx += 256) sw2[idx] = w2[idx];
    if (t < 8) sb2[t] = b2[t];
    __syncthreads();

    const int P0 = blockIdx.x * 512 + t;   // 400 blocks * 512 pixels = 204800
    const int P1 = P0 + 256;
    const int b0 = P0 / HWv, p0 = P0 - b0 * HWv;
    const int b1 = P1 / HWv, p1 = P1 - b1 * HWv;
    const float* xp0 = x + (size_t)b0 * C_ * HWv + p0;
    const float* xp1 = x + (size_t)b1 * C_ * HWv + p1;

    unsigned long long acc0[32], acc1[32];
    #pragma unroll
    for (int m2 = 0; m2 < 32; m2++) { acc0[m2] = 0ULL; acc1[m2] = 0ULL; }

    // Software pipeline: prefetch next 8-channel x block while FMAing current.
    float cur0[8], cur1[8];
    #pragma unroll
    for (int k = 0; k < 8; k++) { cur0[k] = xp0[k * HWv]; cur1[k] = xp1[k * HWv]; }

    #pragma unroll 1
    for (int cb = 0; cb < C_; cb += 8) {
        float nxt0[8], nxt1[8];
        if (cb + 8 < C_) {
            #pragma unroll
            for (int k = 0; k < 8; k++) {
                nxt0[k] = xp0[(cb + 8 + k) * HWv];
                nxt1[k] = xp1[(cb + 8 + k) * HWv];
            }
        }
        #pragma unroll
        for (int k = 0; k < 8; k++) {
            unsigned long long xv0 = pack2(cur0[k], cur0[k]);
            unsigned long long xv1 = pack2(cur1[k], cur1[k]);
            const unsigned long long* wrow = sw1 + (cb + k) * 32;
            #pragma unroll
            for (int m2 = 0; m2 < 32; m2++) {
                unsigned long long wv = wrow[m2];   // one LDS.64 serves 2 FFMA2
                acc0[m2] = ffma2(xv0, wv, acc0[m2]);
                acc1[m2] = ffma2(xv1, wv, acc1[m2]);
            }
        }
        #pragma unroll
        for (int k = 0; k < 8; k++) { cur0[k] = nxt0[k]; cur1[k] = nxt1[k]; }
    }

    // ReLU in place.
    #pragma unroll
    for (int m2 = 0; m2 < 32; m2++) {
        float lo, hi;
        unpack2(acc0[m2], lo, hi);
        acc0[m2] = pack2(fmaxf(lo, 0.f), fmaxf(hi, 0.f));
        unpack2(acc1[m2], lo, hi);
        acc1[m2] = pack2(fmaxf(lo, 0.f), fmaxf(hi, 0.f));
    }

    // Stage 2: off[o] = tanh(W2[o,:] . hid + b2[o]),  o=0..3 -> off_x, 4..7 -> off_y
    float off0[8], off1[8];
    #pragma unroll
    for (int o = 0; o < 8; o++) {
        float s0 = sb2[o], s1 = s0;
        const float* wr = sw2 + o * 64;
        #pragma unroll
        for (int m2 = 0; m2 < 32; m2++) {
            float lo, hi;
            unpack2(acc0[m2], lo, hi);
            s0 = fmaf(lo, wr[2 * m2], s0);
            s0 = fmaf(hi, wr[2 * m2 + 1], s0);
            unpack2(acc1[m2], lo, hi);
            s1 = fmaf(lo, wr[2 * m2], s1);
            s1 = fmaf(hi, wr[2 * m2 + 1], s1);
        }
        off0[o] = tanhf(s0);
        off1[o] = tanhf(s1);
    }

    // Sample coords.
    // x2 = 2w+j : sx = (2*x2+1)/160 - 1 + off_x * (2/160)
    // ix = clip((sx+1)*0.5*79) = (4w+2j+1)*(39.5/160) + off_x*(79/160), clipped [0,79].
    const float A = 0.246875f;   // 39.5/160
    const float Bc = 0.49375f;   // 79/160
    const int h0 = p0 / W_, w0 = p0 - h0 * W_;
    const int h1 = p1 / W_, w1c = p1 - h1 * W_;
    #pragma unroll
    for (int o = 0; o < 4; o++) {
        int j = o & 1, i = o >> 1;
        float ix, iy;
        ix = fminf(fmaxf((float)(4 * w0 + 2 * j + 1) * A + off0[o] * Bc, 0.f), 79.f);
        iy = fminf(fmaxf((float)(4 * h0 + 2 * i + 1) * A + off0[o + 4] * Bc, 0.f), 79.f);
        g_coords[(b0 * 4 + o) * HWv + p0] = make_float2(ix, iy);
        ix = fminf(fmaxf((float)(4 * w1c + 2 * j + 1) * A + off1[o] * Bc, 0.f), 79.f);
        iy = fminf(fmaxf((float)(4 * h1 + 2 * i + 1) * A + off1[o + 4] * Bc, 0.f), 79.f);
        g_coords[(b1 * 4 + o) * HWv + p1] = make_float2(ix, iy);
    }
}

// ---------------------------------------------------------------------------
// Kernel B: bilinear gather. Thread = one (y2, x2) output position; computes
// bilinear weights/offsets ONCE, loops over 256 channels (4 gathers + 1 store).
// Warp = 32 consecutive x2 in one y2 row -> fully coalesced 128B stores.
// ---------------------------------------------------------------------------
__global__ __launch_bounds__(256)
void dysample_sample(const float* __restrict__ x, float* __restrict__ out) {
    const int lane = threadIdx.x & 31;
    const int warp = threadIdx.x >> 5;
    const int y2 = blockIdx.y * 8 + warp;
    const int x2 = blockIdx.x * 32 + lane;
    const int b = blockIdx.z;
    const int h = y2 >> 1, w = x2 >> 1;
    const int o = ((y2 & 1) << 1) | (x2 & 1);

    const float2 cd = g_coords[(b * 4 + o) * HWv + h * W_ + w];
    const float fx = floorf(cd.x), fy = floorf(cd.y);
    const int x0 = (int)fx, y0 = (int)fy;
    const int x1 = min(x0 + 1, W_ - 1), y1 = min(y0 + 1, H_ - 1);
    const float wx = cd.x - fx, wy = cd.y - fy;
    const float w00 = (1.f - wx) * (1.f - wy);
    const float w01 = wx * (1.f - wy);
    const float w10 = (1.f - wx) * wy;
    const float w11 = wx * wy;
    const int o00 = y0 * W_ + x0, o01 = y0 * W_ + x1;
    const int o10 = y1 * W_ + x0, o11 = y1 * W_ + x1;

    const float* xb = x + (size_t)b * C_ * HWv;
    float* ob = out + (size_t)b * C_ * (H2_ * W2_) + y2 * W2_ + x2;

    #pragma unroll 4
    for (int c = 0; c < C_; c++) {
        const float* pl = xb + c * HWv;
        float v = __ldg(pl + o00) * w00 + __ldg(pl + o01) * w01
                + __ldg(pl + o10) * w10 + __ldg(pl + o11) * w11;
        ob[(size_t)c * (H2_ * W2_)] = v;
    }
}

extern "C" void kernel_launch(void* const* d_in, const int* in_sizes, int n_in,
                              void* d_out, int out_size) {
    const float* x  = (const float*)d_in[0];
    const float* w1 = (const float*)d_in[1];
    const float* w2 = (const float*)d_in[2];
    const float* b2 = (const float*)d_in[3];
    float* out = (float*)d_out;

    const int smemA = C_ * 32 * 8 + 512 * 4 + 8 * 4;   // 67616 bytes
    cudaFuncSetAttribute(dysample_offsets,
                         cudaFuncAttributeMaxDynamicSharedMemorySize, smemA);

    dysample_offsets<<<400, 256, smemA>>>(x, w1, w2, b2);

    dim3 gridB(W2_ / 32, H2_ / 8, B_);   // (5, 20, 32)
    dysample_sample<<<gridB, 256>>>(x, out);
}